// round 2
// baseline (speedup 1.0000x reference)
#include <cuda_runtime.h>
#include <math.h>
#include <stdint.h>

// ---------------- problem constants ----------------
#define B_      16
#define HEADS   8
#define G_      64
#define DH      64
#define NSEQ    3131            // 101*31
#define DM      512
#define NH      8
#define L       64
#define DINPROJ 1042            // 2*DM + 2 + 16
#define CONVDIM 514
#define ROWS    1024            // B_*L

#define FINAL_ELEMS (B_*NSEQ*DM)        // 25,649,152
#define INP_ELEMS   (B_*HEADS*G_*DH)    //    524,288

// ---------------- scratch (device globals; no allocs) ----------------
__device__ float g_u[ROWS*DM];
__device__ float g_zx[ROWS*DINPROJ];
__device__ float g_x[ROWS*DM];
__device__ float g_Bv[ROWS];
__device__ float g_Cv[ROWS];
__device__ float g_dtfw[ROWS*NH];
__device__ float g_dtbw[ROWS*NH];
__device__ float g_dcoef[ROWS*NH];
__device__ float g_y[ROWS*DM];
__device__ float g_o[ROWS*DM];
__device__ float g_outp[B_*HEADS*G_*DH];
__device__ float g_M2[B_*DM*DM];        // 16 x 512 x 512

// ---------------- helpers ----------------
__device__ __forceinline__ float softplus_f(float x) {
    return fmaxf(x, 0.f) + log1pf(expf(-fabsf(x)));
}
__device__ __forceinline__ float silu_f(float x) {
    return x / (1.f + expf(-x));
}

// ---------------- kernels ----------------

// u[b,l, h*64+c] = slice_token[b,h,l,c]
__global__ void k_build_u(const float* __restrict__ st) {
    int idx = blockIdx.x * blockDim.x + threadIdx.x;
    if (idx >= ROWS*DM) return;
    int j   = idx & 511;
    int row = idx >> 9;
    int b = row >> 6, l = row & 63;
    int h = j >> 6,  c = j & 63;
    g_u[idx] = st[(((size_t)(b*HEADS + h)*G_ + l)*DH) + c];
}

// Generic NT GEMM: C[m,n] = sum_k A[m*lda+k]*B[n*ldb+k] (+bias[n])
// BM=BN=64, BK=16, 256 threads, 4x4 per thread. K must be mult of 16,
// lda/ldb mult of 4.
__global__ void k_gemm_nt(const float* __restrict__ A, int lda,
                          const float* __restrict__ Bm, int ldb,
                          float* __restrict__ C, int ldc,
                          int M, int N, int K,
                          const float* __restrict__ bias) {
    __shared__ float As[16][68];
    __shared__ float Bs[16][68];
    int tid = threadIdx.x;
    int m0 = blockIdx.y * 64, n0 = blockIdx.x * 64;
    int r  = tid >> 2;
    int c4 = (tid & 3) * 4;
    int ty = tid >> 4, tx = tid & 15;
    float acc[4][4] = {};
    for (int kt = 0; kt < K; kt += 16) {
        float4 av = make_float4(0.f,0.f,0.f,0.f);
        if (m0 + r < M) av = *(const float4*)(A + (size_t)(m0 + r)*lda + kt + c4);
        As[c4+0][r]=av.x; As[c4+1][r]=av.y; As[c4+2][r]=av.z; As[c4+3][r]=av.w;
        float4 bv = make_float4(0.f,0.f,0.f,0.f);
        if (n0 + r < N) bv = *(const float4*)(Bm + (size_t)(n0 + r)*ldb + kt + c4);
        Bs[c4+0][r]=bv.x; Bs[c4+1][r]=bv.y; Bs[c4+2][r]=bv.z; Bs[c4+3][r]=bv.w;
        __syncthreads();
#pragma unroll
        for (int kk = 0; kk < 16; kk++) {
            float a[4], b[4];
#pragma unroll
            for (int i = 0; i < 4; i++) a[i] = As[kk][ty*4 + i];
#pragma unroll
            for (int j = 0; j < 4; j++) b[j] = Bs[kk][tx*4 + j];
#pragma unroll
            for (int i = 0; i < 4; i++)
#pragma unroll
                for (int j = 0; j < 4; j++) acc[i][j] += a[i]*b[j];
        }
        __syncthreads();
    }
#pragma unroll
    for (int i = 0; i < 4; i++) {
        int m = m0 + ty*4 + i;
        if (m >= M) continue;
#pragma unroll
        for (int j = 0; j < 4; j++) {
            int n = n0 + tx*4 + j;
            if (n >= N) continue;
            float v = acc[i][j];
            if (bias) v += bias[n];
            C[(size_t)m*ldc + n] = v;
        }
    }
}

// dt fw/bw: softplus(raw + dt_bias), stored at original l
__global__ void k_dt(const float* __restrict__ dt_bias) {
    int idx = blockIdx.x * blockDim.x + threadIdx.x;
    if (idx >= ROWS*NH) return;
    int h = idx & 7, row = idx >> 3;
    float bsh = dt_bias[h];
    float vf = g_zx[(size_t)row*DINPROJ + 1026 + h] + bsh;
    float vb = g_zx[(size_t)row*DINPROJ + 1034 + h] + bsh;
    g_dtfw[idx] = softplus_f(vf);
    g_dtbw[idx] = softplus_f(vb);
}

// depthwise causal conv (width 3) + silu on xBC channels; split x / Bv / Cv
__global__ void k_conv(const float* __restrict__ conv_w,
                       const float* __restrict__ conv_b) {
    int idx = blockIdx.x * blockDim.x + threadIdx.x;
    if (idx >= ROWS*CONVDIM) return;
    int ch  = idx % CONVDIM;
    int row = idx / CONVDIM;
    int b = row >> 6, l = row & 63;
    float acc = conv_b[ch];
#pragma unroll
    for (int k = 0; k < 3; k++) {
        int lp = l + k - 2;
        if (lp >= 0)
            acc += conv_w[ch*3 + k] * g_zx[(size_t)((b<<6) + lp)*DINPROJ + 512 + ch];
    }
    float s = silu_f(acc);
    if (ch < 512)       g_x[(size_t)row*512 + ch] = s;
    else if (ch == 512) g_Bv[row] = s;
    else                g_Cv[row] = s;
}

// dcoef[row,h] = x[row,:] . fc_D_w[h,:] + D[h]   (8 warps per row)
__global__ void k_dcoef(const float* __restrict__ fcD,
                        const float* __restrict__ Dp) {
    int row  = blockIdx.x;
    int w    = threadIdx.x >> 5;
    int lane = threadIdx.x & 31;
    const float* xr = g_x + (size_t)row*512;
    const float* fr = fcD + (size_t)w*512;
    float s = 0.f;
    for (int k = lane; k < 512; k += 32) s += xr[k]*fr[k];
#pragma unroll
    for (int o = 16; o > 0; o >>= 1) s += __shfl_down_sync(0xffffffffu, s, o);
    if (lane == 0) g_dcoef[row*8 + w] = s + Dp[w];
}

// bidirectional SSM scan, one block per (b,h), 64 threads (d)
// y[l] = (fw_state_before_l * C[l-1]) + (bw contribution) + x*dcoef, then *silu(z)
__global__ void k_scan(const float* __restrict__ A_log) {
    int h = blockIdx.x, b = blockIdx.y;
    int tid = threadIdx.x;
    __shared__ float s_afw[L], s_bfw[L], s_abw[L], s_bbw[L], s_C[L];
    __shared__ float s_acc[64][65];
    {
        int l = tid;
        int row = (b<<6) + l;
        float Ah  = -expf(A_log[h]);
        float dtf = g_dtfw[row*8 + h];
        float dtb = g_dtbw[row*8 + h];
        float Bl  = g_Bv[row];
        s_afw[l] = expf(dtf*Ah); s_bfw[l] = dtf*Bl;
        s_abw[l] = expf(dtb*Ah); s_bbw[l] = dtb*Bl;
        s_C[l]   = g_Cv[row];
    }
    __syncthreads();
    int d = tid;
    const float* xcol = g_x + (size_t)(b<<6)*512 + h*64 + d;
    // forward direction (output shifted by roll)
    float state = 0.f, cprev = 0.f;
    for (int l = 0; l < L; l++) {
        s_acc[d][l] = state * cprev;
        float xv = xcol[(size_t)l*512];
        state = s_afw[l]*state + s_bfw[l]*xv;
        cprev = s_C[l];
    }
    // backward direction (reversed sequence, result written at original pos)
    state = 0.f; cprev = 0.f;
    for (int lr = 0; lr < L; lr++) {
        int lo = 63 - lr;
        float xv = xcol[(size_t)lo*512];
        s_acc[d][lo] += state * cprev;
        state = s_abw[lo]*state + s_bbw[lo]*xv;
        cprev = s_C[lo];
    }
    // + D-term, * silu(z)
    for (int l = 0; l < L; l++) {
        int row = (b<<6) + l;
        float xv = xcol[(size_t)l*512];
        float v  = s_acc[d][l] + xv * g_dcoef[row*8 + h];
        float z  = g_zx[(size_t)row*DINPROJ + h*64 + d];
        v *= silu_f(z);
        g_y[(size_t)row*512 + h*64 + d] = v;
    }
}

// RMS norm (mean over 512) * norm_w, in-place on g_y
__global__ void k_norm(const float* __restrict__ norm_w) {
    int row = blockIdx.x;
    float* yr = g_y + (size_t)row*512;
    int tid = threadIdx.x;                 // 256
    float v0 = yr[tid], v1 = yr[tid + 256];
    float s = v0*v0 + v1*v1;
    __shared__ float red[8];
#pragma unroll
    for (int o = 16; o > 0; o >>= 1) s += __shfl_down_sync(0xffffffffu, s, o);
    if ((tid & 31) == 0) red[tid >> 5] = s;
    __syncthreads();
    if (tid < 32) {
        float t = (tid < 8) ? red[tid] : 0.f;
#pragma unroll
        for (int o = 4; o > 0; o >>= 1) t += __shfl_down_sync(0xffffffffu, t, o);
        if (tid == 0) red[0] = t;
    }
    __syncthreads();
    float scale = rsqrtf(red[0] * (1.f/512.f) + 1e-5f);
    yr[tid]       = v0 * scale * norm_w[tid];
    yr[tid + 256] = v1 * scale * norm_w[tid + 256];
}

// outp[b,h,g,c] = g_o[(b*64+g)*512 + h*64+c]; also writes output segment
__global__ void k_outp(float* __restrict__ out_seg) {
    int idx = blockIdx.x * blockDim.x + threadIdx.x;
    if (idx >= INP_ELEMS) return;
    int c = idx & 63;
    int g = (idx >> 6) & 63;
    int h = (idx >> 12) & 7;
    int b = idx >> 15;
    float v = g_o[(size_t)((b<<6) + g)*512 + h*64 + c];
    g_outp[idx] = v;
    out_seg[idx] = v;
}

// M2[b, h*64+g, d] = sum_c outp[b,h,g,c]*to_out_w[d, h*64+c]
// grid (8 d-tiles, 1, 128 = b*8+h), BM=64(g) BN=64(d) BK=16, 256 thr, 4x4
__global__ void k_gemm_m2(const float* __restrict__ to_out_w) {
    int z = blockIdx.z; int b = z >> 3, h = z & 7;
    const float* A  = g_outp + (size_t)z * 4096;                 // 64x64 (g,c)
    const float* Bm = to_out_w + h*64;                           // rows d, ldb 512
    float* C = g_M2 + (size_t)b*262144 + (size_t)h*64*512;       // rows g, ldc 512
    __shared__ float As[16][68];
    __shared__ float Bs[16][68];
    int tid = threadIdx.x;
    int n0 = blockIdx.x * 64;
    int r = tid >> 2, c4 = (tid & 3) * 4;
    int ty = tid >> 4, tx = tid & 15;
    float acc[4][4] = {};
    for (int kt = 0; kt < 64; kt += 16) {
        float4 av = *(const float4*)(A + (size_t)r*64 + kt + c4);
        As[c4+0][r]=av.x; As[c4+1][r]=av.y; As[c4+2][r]=av.z; As[c4+3][r]=av.w;
        float4 bv = *(const float4*)(Bm + (size_t)(n0 + r)*512 + kt + c4);
        Bs[c4+0][r]=bv.x; Bs[c4+1][r]=bv.y; Bs[c4+2][r]=bv.z; Bs[c4+3][r]=bv.w;
        __syncthreads();
#pragma unroll
        for (int kk = 0; kk < 16; kk++) {
            float a[4], bb[4];
#pragma unroll
            for (int i = 0; i < 4; i++) a[i] = As[kk][ty*4 + i];
#pragma unroll
            for (int j = 0; j < 4; j++) bb[j] = Bs[kk][tx*4 + j];
#pragma unroll
            for (int i = 0; i < 4; i++)
#pragma unroll
                for (int j = 0; j < 4; j++) acc[i][j] += a[i]*bb[j];
        }
        __syncthreads();
    }
#pragma unroll
    for (int i = 0; i < 4; i++)
#pragma unroll
        for (int j = 0; j < 4; j++)
            C[(size_t)(ty*4 + i)*512 + n0 + tx*4 + j] = acc[i][j];
}

// final[b,n,d] = sum_k sw[b, k/64, n, k%64] * M2[b,k,d] + bias[d]
// BM=128(n) BN=128(d) BK=16, 256 threads, 8x8 per thread
__global__ void k_gemm_final(const float* __restrict__ sw,
                             const float* __restrict__ bias,
                             float* __restrict__ out) {
    __shared__ __align__(16) float As[16][132];
    __shared__ __align__(16) float Bs[16][128];
    int b  = blockIdx.z;
    int n0 = blockIdx.y * 128;    // over NSEQ
    int d0 = blockIdx.x * 128;    // over DM
    int tid = threadIdx.x;
    int ty = tid >> 4, tx = tid & 15;
    const float* M2b = g_M2 + (size_t)b * 262144;
    const float* swb = sw + (size_t)b * HEADS * NSEQ * G_;
    float acc[8][8] = {};
    for (int kt = 0; kt < 512; kt += 16) {
        int h  = kt >> 6;
        int ko = kt & 63;
        // A: 128(n) x 16(k) from slice_weights
        {
            int r  = tid >> 2;
            int c4 = (tid & 3) * 4;
#pragma unroll
            for (int half = 0; half < 2; half++) {
                int rr = r + half*64;
                int n = n0 + rr;
                float4 v = make_float4(0.f,0.f,0.f,0.f);
                if (n < NSEQ)
                    v = *(const float4*)(swb + ((size_t)h*NSEQ + n)*64 + ko + c4);
                As[c4+0][rr]=v.x; As[c4+1][rr]=v.y; As[c4+2][rr]=v.z; As[c4+3][rr]=v.w;
            }
        }
        // B: 16(k) x 128(d) from M2
        {
            int rr = tid >> 4;
            int c8 = (tid & 15) * 8;
            const float* p = M2b + (size_t)(kt + rr)*512 + d0 + c8;
            *(float4*)&Bs[rr][c8]     = *(const float4*)p;
            *(float4*)&Bs[rr][c8 + 4] = *(const float4*)(p + 4);
        }
        __syncthreads();
#pragma unroll
        for (int kk = 0; kk < 16; kk++) {
            float a[8], bv[8];
            *(float4*)(a)     = *(const float4*)&As[kk][ty*8];
            *(float4*)(a + 4) = *(const float4*)&As[kk][ty*8 + 4];
            *(float4*)(bv)     = *(const float4*)&Bs[kk][tx*8];
            *(float4*)(bv + 4) = *(const float4*)&Bs[kk][tx*8 + 4];
#pragma unroll
            for (int i = 0; i < 8; i++)
#pragma unroll
                for (int j = 0; j < 8; j++) acc[i][j] += a[i]*bv[j];
        }
        __syncthreads();
    }
    float bb[8];
#pragma unroll
    for (int j = 0; j < 8; j++) bb[j] = bias[d0 + tx*8 + j];
#pragma unroll
    for (int i = 0; i < 8; i++) {
        int n = n0 + ty*8 + i;
        if (n < NSEQ) {
            float* orow = out + ((size_t)b*NSEQ + n)*512 + d0 + tx*8;
#pragma unroll
            for (int j = 0; j < 8; j++) orow[j] = acc[i][j] + bb[j];
        }
    }
}

// ---------------- launch ----------------
extern "C" void kernel_launch(void* const* d_in, const int* in_sizes, int n_in,
                              void* d_out, int out_size) {
    const float* st       = (const float*)d_in[0];   // slice_token
    const float* sw       = (const float*)d_in[1];   // slice_weights
    const float* w_in     = (const float*)d_in[2];
    const float* conv_w   = (const float*)d_in[3];
    const float* conv_b   = (const float*)d_in[4];
    const float* dt_bias  = (const float*)d_in[5];
    const float* A_log    = (const float*)d_in[6];
    const float* Dp       = (const float*)d_in[7];
    const float* fcD      = (const float*)d_in[8];
    const float* norm_w   = (const float*)d_in[9];
    const float* w_out    = (const float*)d_in[10];
    const float* to_out_w = (const float*)d_in[11];
    const float* to_out_b = (const float*)d_in[12];

    float* out      = (float*)d_out;
    float* inp_seg  = out + (size_t)FINAL_ELEMS;
    float* outp_seg = out + (size_t)FINAL_ELEMS + INP_ELEMS;

    float *p_u, *p_zx, *p_y, *p_o;
    cudaGetSymbolAddress((void**)&p_u,  g_u);
    cudaGetSymbolAddress((void**)&p_zx, g_zx);
    cudaGetSymbolAddress((void**)&p_y,  g_y);
    cudaGetSymbolAddress((void**)&p_o,  g_o);

    // 1. gather u
    k_build_u<<<(ROWS*DM + 255)/256, 256>>>(st);
    // 2. in-projection: zx = u @ w_in^T  (1024 x 1042, K=512)
    k_gemm_nt<<<dim3((DINPROJ + 63)/64, ROWS/64), 256>>>(
        p_u, DM, w_in, DM, p_zx, DINPROJ, ROWS, DINPROJ, DM, nullptr);
    // 3. dt activations
    k_dt<<<(ROWS*NH + 255)/256, 256>>>(dt_bias);
    // 4. conv + silu + split
    k_conv<<<(ROWS*CONVDIM + 255)/256, 256>>>(conv_w, conv_b);
    // 5. dcoef
    k_dcoef<<<ROWS, 256>>>(fcD, Dp);
    // 6. bidirectional scan (+ D-term + silu(z) gate)
    k_scan<<<dim3(HEADS, B_), 64>>>(A_log);
    // 7. RMS norm
    k_norm<<<ROWS, 256>>>(norm_w);
    // 8. out = y @ w_out^T  (1024 x 512, K=512)
    k_gemm_nt<<<dim3(DM/64, ROWS/64), 256>>>(
        p_y, DM, w_out, DM, p_o, DM, ROWS, DM, DM, nullptr);
    // 9. outp layout + write segment 3
    k_outp<<<(INP_ELEMS + 255)/256, 256>>>(outp_seg);
    // 10. inp passthrough (segment 2)
    cudaMemcpyAsync(inp_seg, st, (size_t)INP_ELEMS * sizeof(float),
                    cudaMemcpyDeviceToDevice);
    // 11. M2 = per-(b,h) outp @ to_out_w_block^T
    k_gemm_m2<<<dim3(8, 1, B_*HEADS), 256>>>(to_out_w);
    // 12. final = SW @ M2 + bias  (16 batched 3131x512x512)
    k_gemm_final<<<dim3(DM/128, (NSEQ + 127)/128, B_), 256>>>(sw, to_out_b, out);
}